// round 7
// baseline (speedup 1.0000x reference)
#include <cuda_runtime.h>
#include <cuda_bf16.h>
#include <cstdint>

#define SAMP_BLOCKS 64
#define K2_MAXBLK   65536

// Device-global scratch (no allocations). Every word is rewritten on every
// launch before being read -> no cross-call state, deterministic.
__device__ unsigned g_spart[SAMP_BLOCKS];
__device__ unsigned g_guess_pack;
__device__ unsigned g_partial[K2_MAXBLK];
__device__ unsigned g_act_pack;
__device__ unsigned g_mismatch;

// ---------------------------------------------------------------------------
// Robust small-integer scalar decode (int32/int64/float32/float64).
// ---------------------------------------------------------------------------
__device__ __forceinline__ int decode_scalar(const int* p, int dflt) {
    if (p == nullptr) return dflt;
    int w0 = p[0];
    if (w0 >= -1000000 && w0 <= 1000000) {
        if (w0 != 0) return w0;
        int w1 = p[1];
        if (w1 == 0) return 0;
        double d = __hiloint2double(w1, w0);
        if (d >= -1e6 && d <= 1e6) return (int)d;
        return 0;
    }
    float f = __int_as_float(w0);
    if (f >= -1e6f && f <= 1e6f) return (int)f;
    int w1 = p[1];
    double d = __hiloint2double(w1, w0);
    if (d >= -1e6 && d <= 1e6) return (int)d;
    return dflt;
}

// ---------------------------------------------------------------------------
// Shift transform descriptor: pack = mode | (shift << 2)
//   mode 0 = zeros (bw==0), 1 = int8-wrap trunc (shift<1), 2 = psto(shift)
// ---------------------------------------------------------------------------
__device__ __forceinline__ unsigned make_pack(unsigned rng, int mu) {
    if (rng == 0u) return 0u;
    int bw = (int)ceilf(log2f(fmaxf((float)rng, 1.0f)));
    int shift = bw - mu;
    if (shift < 1) return 1u;
    return 2u | ((unsigned)shift << 2);
}

// ---------------------------------------------------------------------------
// Pseudo-stochastic shift quantizer (faithful _psto_shift, s >= 1).
// Verified bit-exact vs reference (rel_err = 0.0 in R4/R5/R6).
// ---------------------------------------------------------------------------
__device__ __forceinline__ int uw_psto(int x, int s) {
    int rt   = x >> s;
    int prob = x & ((1 << s) - 1);
    int hs   = s >> 1;
    int qprob = prob >> hs;
    int prn   = (prob & ((1 << hs) - 1)) * (1 + (s & 1));
    int sgn   = (x > 0) - (x < 0);
    int dec   = (qprob <= prn) ? 0 : sgn;
    return min(127, max(-127, rt + dec));
}

__device__ __forceinline__ unsigned max4abs(int4 v) {
    unsigned a0 = (unsigned)(v.x < 0 ? -v.x : v.x);
    unsigned a1 = (unsigned)(v.y < 0 ? -v.y : v.y);
    unsigned a2 = (unsigned)(v.z < 0 ? -v.z : v.z);
    unsigned a3 = (unsigned)(v.w < 0 ? -v.w : v.w);
    return max(max(a0, a1), max(a2, a3));
}

// Apply the packed transform to one int4 grad + int4 weight group.
__device__ __forceinline__ void uw_apply(int4 gv, int4 wv, int mode, int s,
                                         float4& ow, float4& og) {
    int gx[4] = { gv.x, gv.y, gv.z, gv.w };
    int wi[4] = { wv.x, wv.y, wv.z, wv.w };
    float o_g[4], o_w[4];
#pragma unroll
    for (int k = 0; k < 4; k++) {
        int gq;
        if (mode == 0)      gq = 0;
        else if (mode == 1) gq = (int)(signed char)gx[k];   // wraps like astype(int8)
        else                gq = uw_psto(gx[k], s);
        int nw = wi[k] - gq;
        nw = min(127, max(-127, nw));
        o_g[k] = (float)gq;
        o_w[k] = (float)nw;
    }
    ow = make_float4(o_w[0], o_w[1], o_w[2], o_w[3]);
    og = make_float4(o_g[0], o_g[1], o_g[2], o_g[3]);
}

__device__ __forceinline__ unsigned block_reduce_max256(unsigned m, unsigned* s_red) {
    m = __reduce_max_sync(0xffffffffu, m);
    int lane = threadIdx.x & 31;
    int wid  = threadIdx.x >> 5;
    if (lane == 0) s_red[wid] = m;
    __syncthreads();
    unsigned v = 0u;
    if (wid == 0) {
        v = (lane < (int)(blockDim.x >> 5)) ? s_red[lane] : 0u;
        v = __reduce_max_sync(0xffffffffu, v);
    }
    return v;  // valid in warp 0
}

// ---------------------------------------------------------------------------
// K1: strided subsample of |grad| -> g_spart[block]. ~65K int4 samples.
// ---------------------------------------------------------------------------
__global__ void uw_sample_kernel(const int4* __restrict__ g, long n4, long st) {
    __shared__ unsigned s_red[32];
    long gid = (long)blockIdx.x * blockDim.x + threadIdx.x;
    unsigned m = 0u;
#pragma unroll
    for (int k = 0; k < 4; k++) {
        long idx = (gid * 4 + k) * st;
        if (idx < n4) m = max(m, max4abs(__ldg(&g[idx])));
    }
    unsigned bm = block_reduce_max256(m, s_red);
    if (threadIdx.x == 0) g_spart[blockIdx.x] = bm;
}

// ---------------------------------------------------------------------------
// K1b: reduce 64 sample-partials -> guessed transform pack. 64 threads.
// ---------------------------------------------------------------------------
__global__ void uw_guess_kernel(const int* __restrict__ p_mu) {
    __shared__ unsigned sm[2];
    unsigned m = g_spart[threadIdx.x];
    m = __reduce_max_sync(0xffffffffu, m);
    int lane = threadIdx.x & 31;
    int wid  = threadIdx.x >> 5;
    if (lane == 0) sm[wid] = m;
    __syncthreads();
    if (threadIdx.x == 0) {
        unsigned rng = max(sm[0], sm[1]);
        g_guess_pack = make_pack(rng, decode_scalar(p_mu, 7));
    }
}

// ---------------------------------------------------------------------------
// K2: single fused main pass. Reads grad+weight once; computes the TRUE
// per-block max (partials) and writes outputs using the GUESSED transform.
// ---------------------------------------------------------------------------
__global__ void uw_main_kernel(
    const int4* __restrict__ w4,
    const int4* __restrict__ g4,
    float4* __restrict__ ow4,
    float4* __restrict__ og4,
    long n4)
{
    __shared__ unsigned s_red[32];
    unsigned pack = g_guess_pack;
    int mode = (int)(pack & 3u);
    int s    = (int)(pack >> 2);

    long i0     = (long)blockIdx.x * blockDim.x + threadIdx.x;
    long stride = (long)gridDim.x * blockDim.x;

    unsigned m = 0u;
    for (long i = i0; i < n4; i += stride) {
        int4 gv = __ldg(&g4[i]);
        int4 wv = __ldg(&w4[i]);
        m = max(m, max4abs(gv));
        float4 ow, og;
        uw_apply(gv, wv, mode, s, ow, og);
        ow4[i] = ow;
        og4[i] = og;
    }
    unsigned bm = block_reduce_max256(m, s_red);
    if (threadIdx.x == 0) g_partial[blockIdx.x] = bm;
}

// ---------------------------------------------------------------------------
// K3: reduce true partials -> actual pack; write grad_exp; set mismatch flag.
// Single block of 256 threads.
// ---------------------------------------------------------------------------
__global__ void uw_verify_kernel(
    const int* __restrict__ p_err_exp,
    const int* __restrict__ p_act_in_exp,
    const int* __restrict__ p_mu,
    float* __restrict__ out_exp,
    int nblocks)
{
    __shared__ unsigned s_red[32];
    unsigned m = 0u;
    for (int i = threadIdx.x; i < nblocks; i += blockDim.x)
        m = max(m, g_partial[i]);
    unsigned rng = block_reduce_max256(m, s_red);
    if (threadIdx.x == 0) {
        int mu = decode_scalar(p_mu, 7);
        unsigned pack = make_pack(rng, mu);
        g_act_pack = pack;
        g_mismatch = (pack != g_guess_pack) ? 1u : 0u;
        int mode = (int)(pack & 3u);
        int gs   = (mode == 2) ? (int)(pack >> 2) : 0;
        int ee = decode_scalar(p_err_exp, -10);
        int ae = decode_scalar(p_act_in_exp, -7);
        *out_exp = (float)(ee + gs + ae);
    }
}

// ---------------------------------------------------------------------------
// K4: fixup. If the guess matched (overwhelmingly likely), exits instantly.
// Otherwise rewrites all outputs with the actual transform -> always correct.
// ---------------------------------------------------------------------------
__global__ void uw_fixup_kernel(
    const int4* __restrict__ w4,
    const int4* __restrict__ g4,
    float4* __restrict__ ow4,
    float4* __restrict__ og4,
    long n4)
{
    if (g_mismatch == 0u) return;
    unsigned pack = g_act_pack;
    int mode = (int)(pack & 3u);
    int s    = (int)(pack >> 2);

    long i0     = (long)blockIdx.x * blockDim.x + threadIdx.x;
    long stride = (long)gridDim.x * blockDim.x;
    for (long i = i0; i < n4; i += stride) {
        int4 gv = __ldg(&g4[i]);
        int4 wv = __ldg(&w4[i]);
        float4 ow, og;
        uw_apply(gv, wv, mode, s, ow, og);
        ow4[i] = ow;
        og4[i] = og;
    }
}

// ---------------------------------------------------------------------------
// Launch. Inputs: weight int32[N] (promoted int8), grad int32[N],
// err_exp, act_in_exp, mu (int32 scalars).
// Output: float32[2N+1] = concat(new_weight, grad, grad_exp).
// ---------------------------------------------------------------------------
extern "C" void kernel_launch(void* const* d_in, const int* in_sizes, int n_in,
                              void* d_out, int out_size)
{
    const int4* w4 = (const int4*)d_in[0];
    const int4* g4 = (const int4*)d_in[1];
    const int* p_err = (n_in > 2) ? (const int*)d_in[2] : nullptr;
    const int* p_act = (n_in > 3) ? (const int*)d_in[3] : nullptr;
    const int* p_mu  = (n_in > 4) ? (const int*)d_in[4] : nullptr;

    long N  = (long)in_sizes[0];
    long n4 = N >> 2;

    float* out   = (float*)d_out;
    float4* ow4  = (float4*)out;
    float4* og4  = (float4*)(out + N);
    float* out_e = out + 2 * N;

    // Sampling stride so SAMP_BLOCKS*256*4 samples span the whole array.
    long st = n4 / ((long)SAMP_BLOCKS * 256 * 4);
    if (st < 1) st = 1;

    long want = (n4 + 255) / 256;
    int blocks = (want > K2_MAXBLK) ? K2_MAXBLK : (int)want;

    uw_sample_kernel<<<SAMP_BLOCKS, 256>>>(g4, n4, st);
    uw_guess_kernel<<<1, 64>>>(p_mu);
    uw_main_kernel<<<blocks, 256>>>(w4, g4, ow4, og4, n4);
    uw_verify_kernel<<<1, 256>>>(p_err, p_act, p_mu, out_e, blocks);
    uw_fixup_kernel<<<blocks, 256>>>(w4, g4, ow4, og4, n4);
}

// round 8
// speedup vs baseline: 1.5812x; 1.5812x over previous
#include <cuda_runtime.h>
#include <cuda_bf16.h>
#include <cstdint>

#define SAMP_BLOCKS 64
#define MAIN_BLOCKS 1184
#define TPB         256

// Device-global scratch (no allocations). Every word is rewritten on every
// launch before being read -> no cross-call state, deterministic.
__device__ unsigned g_spart[SAMP_BLOCKS];
__device__ unsigned g_guess_pack;
__device__ unsigned g_partial[MAIN_BLOCKS];
__device__ unsigned g_act_pack;
__device__ unsigned g_mismatch;

// ---------------------------------------------------------------------------
// Robust small-integer scalar decode (int32/int64/float32/float64).
// ---------------------------------------------------------------------------
__device__ __forceinline__ int decode_scalar(const int* p, int dflt) {
    if (p == nullptr) return dflt;
    int w0 = p[0];
    if (w0 >= -1000000 && w0 <= 1000000) {
        if (w0 != 0) return w0;
        int w1 = p[1];
        if (w1 == 0) return 0;
        double d = __hiloint2double(w1, w0);
        if (d >= -1e6 && d <= 1e6) return (int)d;
        return 0;
    }
    float f = __int_as_float(w0);
    if (f >= -1e6f && f <= 1e6f) return (int)f;
    int w1 = p[1];
    double d = __hiloint2double(w1, w0);
    if (d >= -1e6 && d <= 1e6) return (int)d;
    return dflt;
}

// ---------------------------------------------------------------------------
// Transform descriptor: pack = mode | (shift << 2)
//   mode 0 = zeros (bw==0), 1 = int8-wrap trunc (shift<1), 2 = psto(shift)
// ---------------------------------------------------------------------------
__device__ __forceinline__ unsigned make_pack(unsigned rng, int mu) {
    if (rng == 0u) return 0u;
    int bw = (int)ceilf(log2f(fmaxf((float)rng, 1.0f)));
    int shift = bw - mu;
    if (shift < 1) return 1u;
    return 2u | ((unsigned)shift << 2);
}

// ---------------------------------------------------------------------------
// Pseudo-stochastic shift quantizer (bit-exact vs reference, s >= 1).
// ---------------------------------------------------------------------------
__device__ __forceinline__ int uw_psto(int x, int s) {
    int rt   = x >> s;
    int prob = x & ((1 << s) - 1);
    int hs   = s >> 1;
    int qprob = prob >> hs;
    int prn   = (prob & ((1 << hs) - 1)) * (1 + (s & 1));
    int sgn   = (x > 0) - (x < 0);
    int dec   = (qprob <= prn) ? 0 : sgn;
    return min(127, max(-127, rt + dec));
}

__device__ __forceinline__ unsigned max4abs(int4 v) {
    unsigned a0 = (unsigned)(v.x < 0 ? -v.x : v.x);
    unsigned a1 = (unsigned)(v.y < 0 ? -v.y : v.y);
    unsigned a2 = (unsigned)(v.z < 0 ? -v.z : v.z);
    unsigned a3 = (unsigned)(v.w < 0 ? -v.w : v.w);
    return max(max(a0, a1), max(a2, a3));
}

__device__ __forceinline__ void uw_apply(int4 gv, int4 wv, int mode, int s,
                                         float4& ow, float4& og) {
    int gx[4] = { gv.x, gv.y, gv.z, gv.w };
    int wi[4] = { wv.x, wv.y, wv.z, wv.w };
    float o_g[4], o_w[4];
#pragma unroll
    for (int k = 0; k < 4; k++) {
        int gq;
        if (mode == 0)      gq = 0;
        else if (mode == 1) gq = (int)(signed char)gx[k];   // wraps like astype(int8)
        else                gq = uw_psto(gx[k], s);
        int nw = wi[k] - gq;
        nw = min(127, max(-127, nw));
        o_g[k] = (float)gq;
        o_w[k] = (float)nw;
    }
    ow = make_float4(o_w[0], o_w[1], o_w[2], o_w[3]);
    og = make_float4(o_g[0], o_g[1], o_g[2], o_g[3]);
}

__device__ __forceinline__ unsigned block_reduce_max256(unsigned m, unsigned* s_red) {
    m = __reduce_max_sync(0xffffffffu, m);
    int lane = threadIdx.x & 31;
    int wid  = threadIdx.x >> 5;
    if (lane == 0) s_red[wid] = m;
    __syncthreads();
    unsigned v = 0u;
    if (wid == 0) {
        v = (lane < (int)(blockDim.x >> 5)) ? s_red[lane] : 0u;
        v = __reduce_max_sync(0xffffffffu, v);
    }
    return v;  // valid in warp 0
}

// ---------------------------------------------------------------------------
// K1: strided subsample of |grad| -> g_spart[block]. ~65K int4 samples (1MB).
// ---------------------------------------------------------------------------
__global__ void uw_sample_kernel(const int4* __restrict__ g, long n4, long st) {
    __shared__ unsigned s_red[32];
    long gid = (long)blockIdx.x * blockDim.x + threadIdx.x;
    unsigned m = 0u;
#pragma unroll
    for (int k = 0; k < 4; k++) {
        long idx = (gid * 4 + k) * st;
        if (idx < n4) m = max(m, max4abs(__ldg(&g[idx])));
    }
    unsigned bm = block_reduce_max256(m, s_red);
    if (threadIdx.x == 0) g_spart[blockIdx.x] = bm;
}

// ---------------------------------------------------------------------------
// K1b: reduce 64 sample-partials -> guessed transform pack. 64 threads.
// ---------------------------------------------------------------------------
__global__ void uw_guess_kernel(const int* __restrict__ p_mu) {
    __shared__ unsigned sm[2];
    unsigned m = g_spart[threadIdx.x];
    m = __reduce_max_sync(0xffffffffu, m);
    int lane = threadIdx.x & 31;
    int wid  = threadIdx.x >> 5;
    if (lane == 0) sm[wid] = m;
    __syncthreads();
    if (threadIdx.x == 0) {
        unsigned rng = max(sm[0], sm[1]);
        g_guess_pack = make_pack(rng, decode_scalar(p_mu, 7));
    }
}

// ---------------------------------------------------------------------------
// K2: single fused main pass (grid-stride, MAIN_BLOCKS). Reads grad+weight
// once; computes TRUE per-block max (-> g_partial) and writes outputs using
// the GUESSED transform.
// ---------------------------------------------------------------------------
__global__ void uw_main_kernel(
    const int4* __restrict__ w4,
    const int4* __restrict__ g4,
    float4* __restrict__ ow4,
    float4* __restrict__ og4,
    long n4)
{
    __shared__ unsigned s_red[32];
    unsigned pack = g_guess_pack;
    int mode = (int)(pack & 3u);
    int s    = (int)(pack >> 2);

    long i0     = (long)blockIdx.x * blockDim.x + threadIdx.x;
    long stride = (long)gridDim.x * blockDim.x;

    unsigned m = 0u;
    for (long i = i0; i < n4; i += stride) {
        int4 gv = __ldg(&g4[i]);
        int4 wv = __ldg(&w4[i]);
        m = max(m, max4abs(gv));
        float4 ow, og;
        uw_apply(gv, wv, mode, s, ow, og);
        ow4[i] = ow;
        og4[i] = og;
    }
    unsigned bm = block_reduce_max256(m, s_red);
    if (threadIdx.x == 0) g_partial[blockIdx.x] = bm;
}

// ---------------------------------------------------------------------------
// K3: reduce MAIN_BLOCKS true partials -> actual pack; write grad_exp; set
// mismatch flag. One block; 4 independent accumulators/thread for MLP.
// ---------------------------------------------------------------------------
__global__ void uw_verify_kernel(
    const int* __restrict__ p_err_exp,
    const int* __restrict__ p_act_in_exp,
    const int* __restrict__ p_mu,
    float* __restrict__ out_exp)
{
    __shared__ unsigned s_red[32];
    unsigned m0 = 0u, m1 = 0u, m2 = 0u, m3 = 0u;
    for (int i = threadIdx.x * 4; i < MAIN_BLOCKS; i += blockDim.x * 4) {
        m0 = max(m0, g_partial[i]);
        if (i + 1 < MAIN_BLOCKS) m1 = max(m1, g_partial[i + 1]);
        if (i + 2 < MAIN_BLOCKS) m2 = max(m2, g_partial[i + 2]);
        if (i + 3 < MAIN_BLOCKS) m3 = max(m3, g_partial[i + 3]);
    }
    unsigned m = max(max(m0, m1), max(m2, m3));
    unsigned rng = block_reduce_max256(m, s_red);
    if (threadIdx.x == 0) {
        int mu = decode_scalar(p_mu, 7);
        unsigned pack = make_pack(rng, mu);
        g_act_pack = pack;
        g_mismatch = (pack != g_guess_pack) ? 1u : 0u;
        int mode = (int)(pack & 3u);
        int gs   = (mode == 2) ? (int)(pack >> 2) : 0;
        int ee = decode_scalar(p_err_exp, -10);
        int ae = decode_scalar(p_act_in_exp, -7);
        *out_exp = (float)(ee + gs + ae);
    }
}

// ---------------------------------------------------------------------------
// K4: fixup. If guess matched (overwhelmingly likely), exits immediately.
// Otherwise rewrites all outputs with the actual transform -> always correct.
// ---------------------------------------------------------------------------
__global__ void uw_fixup_kernel(
    const int4* __restrict__ w4,
    const int4* __restrict__ g4,
    float4* __restrict__ ow4,
    float4* __restrict__ og4,
    long n4)
{
    if (g_mismatch == 0u) return;
    unsigned pack = g_act_pack;
    int mode = (int)(pack & 3u);
    int s    = (int)(pack >> 2);

    long i0     = (long)blockIdx.x * blockDim.x + threadIdx.x;
    long stride = (long)gridDim.x * blockDim.x;
    for (long i = i0; i < n4; i += stride) {
        int4 gv = __ldg(&g4[i]);
        int4 wv = __ldg(&w4[i]);
        float4 ow, og;
        uw_apply(gv, wv, mode, s, ow, og);
        ow4[i] = ow;
        og4[i] = og;
    }
}

// ---------------------------------------------------------------------------
// Launch. Inputs: weight int32[N] (promoted int8), grad int32[N],
// err_exp, act_in_exp, mu (int32 scalars).
// Output: float32[2N+1] = concat(new_weight, grad, grad_exp).
// ---------------------------------------------------------------------------
extern "C" void kernel_launch(void* const* d_in, const int* in_sizes, int n_in,
                              void* d_out, int out_size)
{
    const int4* w4 = (const int4*)d_in[0];
    const int4* g4 = (const int4*)d_in[1];
    const int* p_err = (n_in > 2) ? (const int*)d_in[2] : nullptr;
    const int* p_act = (n_in > 3) ? (const int*)d_in[3] : nullptr;
    const int* p_mu  = (n_in > 4) ? (const int*)d_in[4] : nullptr;

    long N  = (long)in_sizes[0];
    long n4 = N >> 2;

    float* out   = (float*)d_out;
    float4* ow4  = (float4*)out;
    float4* og4  = (float4*)(out + N);
    float* out_e = out + 2 * N;

    long st = n4 / ((long)SAMP_BLOCKS * 256 * 4);
    if (st < 1) st = 1;

    uw_sample_kernel<<<SAMP_BLOCKS, TPB>>>(g4, n4, st);
    uw_guess_kernel<<<1, 64>>>(p_mu);
    uw_main_kernel<<<MAIN_BLOCKS, TPB>>>(w4, g4, ow4, og4, n4);
    uw_verify_kernel<<<1, TPB>>>(p_err, p_act, p_mu, out_e);
    uw_fixup_kernel<<<MAIN_BLOCKS, TPB>>>(w4, g4, ow4, og4, n4);
}